// round 4
// baseline (speedup 1.0000x reference)
#include <cuda_runtime.h>

#define NH 18
#define NP 9
#define RW 20   // padded row width (floats) = 80B -> rows 16B-aligned

typedef unsigned long long u64;

// ---- smem float offsets (row bases 16B-aligned) ----
#define S_WF   0      // 6  rows
#define S_WM   120    // 36 rows
#define S_WUM  840    // 18 rows (Wu rows 0..17, message part)
#define S_WUH  1200   // 18 rows (Wu[18:36]+Wu[36:54] folded, U==h there)
#define S_WR   1560   // 5 rows
#define S_BF   1660
#define S_BM   1680
#define S_BU   1700
#define S_BR   1720
#define S_TOT  1728

__device__ __forceinline__ u64 dup2(float v){
    u64 r; asm("mov.b64 %0, {%1,%1};" : "=l"(r) : "f"(v)); return r;
}
__device__ __forceinline__ u64 pk2(float lo, float hi){
    u64 r; asm("mov.b64 %0, {%1,%2};" : "=l"(r) : "f"(lo), "f"(hi)); return r;
}
__device__ __forceinline__ void upk2(u64 v, float& lo, float& hi){
    asm("mov.b64 {%0,%1}, %2;" : "=f"(lo), "=f"(hi) : "l"(v));
}
__device__ __forceinline__ u64 fma2(u64 a, u64 b, u64 c){
    u64 d; asm("fma.rn.f32x2 %0, %1, %2, %3;" : "=l"(d) : "l"(a), "l"(b), "l"(c));
    return d;
}
__device__ __forceinline__ float tanhap(float x){
    float r; asm("tanh.approx.f32 %0, %1;" : "=f"(r) : "f"(x)); return r;
}

// 18-float row as 9 u64 pairs: 4x LDS.128 + 1x LDS.64 (broadcast across lanes)
__device__ __forceinline__ void ldrow9(const float* s, int off, u64 w[NP]){
    const ulonglong2* p = (const ulonglong2*)(s + off);
    ulonglong2 q0 = p[0], q1 = p[1];
    ulonglong2 q2 = *(const ulonglong2*)(s + off + 8);
    ulonglong2 q3 = *(const ulonglong2*)(s + off + 12);
    w[0]=q0.x; w[1]=q0.y; w[2]=q1.x; w[3]=q1.y;
    w[4]=q2.x; w[5]=q2.y; w[6]=q3.x; w[7]=q3.y;
    w[8] = *(const u64*)(s + off + 16);
}

// 5 threads per batch element (one per ring node), groups packed in a warp:
// lanes [0..29] = 6 groups of 5; lanes 30,31 idle-duplicate (never store).
__global__ void __launch_bounds__(128, 4) mp_kernel(
    const float* __restrict__ x,
    const float* __restrict__ Wf, const float* __restrict__ bf,
    const float* __restrict__ Wm, const float* __restrict__ bm,
    const float* __restrict__ Wu, const float* __restrict__ bu,
    const float* __restrict__ Wr, const float* __restrict__ br,
    float* __restrict__ out, int n)
{
    __shared__ __align__(16) float s[S_TOT];
    const int t = threadIdx.x;
    for (int k = t; k < 6*NH;  k += 128){ int r=k/NH, c=k%NH; s[S_WF + r*RW + c] = Wf[k]; }
    for (int k = t; k < 36*NH; k += 128){ int r=k/NH, c=k%NH; s[S_WM + r*RW + c] = Wm[k]; }
    for (int k = t; k < 18*NH; k += 128){
        int r=k/NH, c=k%NH;
        s[S_WUM + r*RW + c] = Wu[k];
        s[S_WUH + r*RW + c] = Wu[324 + k] + Wu[648 + k];   // fold duplicated h columns
    }
    for (int k = t; k < 90; k += 128){ int r=k/NH, c=k%NH; s[S_WR + r*RW + c] = Wr[k]; }
    if (t < NH){ s[S_BF+t] = bf[t]; s[S_BM+t] = bm[t]; s[S_BU+t] = bu[t]; }
    if (t == 0) s[S_BR] = br[0];
    __syncthreads();

    const int lane = t & 31;
    const int warp = t >> 5;
    const int grp  = lane / 5;                 // 0..6 (6 is the idle spill)
    const int node = lane - grp * 5;           // 0..4 (garbage for lanes 30,31)
    const int gvalid = (lane < 30);
    const int base = gvalid ? grp * 5 : 25;    // shfl base lane within warp group

    // element index; clamp for idle/tail lanes (they compute, never store)
    int elem = (blockIdx.x * 4 + warp) * 6 + (gvalid ? grp : 0);
    const int store_ok = gvalid && (node == 0) && (elem < n);
    if (elem >= n) elem = n - 1;

    // ---- x for own node: 6 floats, 8B-aligned (elem*30 + node*6 is even) ----
    float xv[6];
    {
        const float2* p = (const float2*)(x + (long long)elem * 30 + node * 6);
        float2 a = p[0], c = p[1], d = p[2];
        xv[0]=a.x; xv[1]=a.y; xv[2]=c.x; xv[3]=c.y; xv[4]=d.x; xv[5]=d.y;
    }

    // ======== layer 1: h_own = tanh(x @ Wf + bf) ========
    u64 acc[NP];
    ldrow9(s, S_BF, acc);
    #pragma unroll
    for (int f = 0; f < 6; f++){
        u64 w[NP]; ldrow9(s, S_WF + f*RW, w);
        u64 a = dup2(xv[f]);
        #pragma unroll
        for (int p = 0; p < NP; p++) acc[p] = fma2(a, w[p], acc[p]);
    }
    float h_own[NH];
    #pragma unroll
    for (int p = 0; p < NP; p++){
        float lo, hi; upk2(acc[p], lo, hi);
        h_own[2*p]   = tanhap(lo);
        h_own[2*p+1] = tanhap(hi);
    }

    // ---- exchange: h_next from node (node+1)%5 in my group ----
    const int nn = base + (node == 4 ? 0 : node + 1);
    float h_next[NH];
    #pragma unroll
    for (int e = 0; e < NH; e++) h_next[e] = __shfl_sync(0xffffffffu, h_own[e], nn);

    // ======== layer M: M_own = tanh([h_own, h_next] @ Wm + bm) ========
    ldrow9(s, S_BM, acc);
    #pragma unroll
    for (int e = 0; e < NH; e++){
        u64 w[NP]; ldrow9(s, S_WM + e*RW, w);
        u64 a = dup2(h_own[e]);
        #pragma unroll
        for (int p = 0; p < NP; p++) acc[p] = fma2(a, w[p], acc[p]);
    }
    #pragma unroll
    for (int e = 0; e < NH; e++){
        u64 w[NP]; ldrow9(s, S_WM + (NH + e)*RW, w);
        u64 a = dup2(h_next[e]);
        #pragma unroll
        for (int p = 0; p < NP; p++) acc[p] = fma2(a, w[p], acc[p]);
    }
    float M_own[NH];
    #pragma unroll
    for (int p = 0; p < NP; p++){
        float lo, hi; upk2(acc[p], lo, hi);
        M_own[2*p]   = tanhap(lo);
        M_own[2*p+1] = tanhap(hi);
    }

    // ---- exchange: M_prev from node (node+4)%5 (reuse h_next storage) ----
    const int pn = base + (node == 0 ? 4 : node - 1);
    #pragma unroll
    for (int e = 0; e < NH; e++) h_next[e] = __shfl_sync(0xffffffffu, M_own[e], pn);

    // ======== layer U: U_own = tanh(M_prev @ WuM + h_own @ WuH + bu) ========
    ldrow9(s, S_BU, acc);
    #pragma unroll
    for (int e = 0; e < NH; e++){
        u64 w[NP]; ldrow9(s, S_WUM + e*RW, w);
        u64 a = dup2(h_next[e]);                  // M_prev
        #pragma unroll
        for (int p = 0; p < NP; p++) acc[p] = fma2(a, w[p], acc[p]);
    }
    #pragma unroll
    for (int e = 0; e < NH; e++){
        u64 w[NP]; ldrow9(s, S_WUH + e*RW, w);
        u64 a = dup2(h_own[e]);
        #pragma unroll
        for (int p = 0; p < NP; p++) acc[p] = fma2(a, w[p], acc[p]);
    }

    // ======== readout partial: r = U_own . Wr[node] ========
    u64 racc = 0;
    {
        u64 wr[NP]; ldrow9(s, S_WR + node*RW, wr);
        #pragma unroll
        for (int p = 0; p < NP; p++){
            float lo, hi; upk2(acc[p], lo, hi);
            u64 u2 = pk2(tanhap(lo), tanhap(hi));
            racc = fma2(u2, wr[p], racc);
        }
    }
    float r0, r1; upk2(racc, r0, r1);
    float r = r0 + r1;

    // ---- reduce across the 5 group lanes ----
    r += __shfl_sync(0xffffffffu, r, base + 1);
    r += __shfl_sync(0xffffffffu, r, base + 2);   // careful: do tree on raw partials
    // NOTE: the two lines above would double-count with a naive tree; use
    // explicit gather-from-all instead (overwritten below).
    // Recompute cleanly: gather each lane's partial.
    // (r was clobbered; redo with saved partial)
    // -- implemented properly below --
    (void)r;

    // proper reduction: gather 4 partners' partials explicitly
    float mine = r0 + r1;
    float p1 = __shfl_sync(0xffffffffu, mine, base + 1);
    float p2 = __shfl_sync(0xffffffffu, mine, base + 2);
    float p3 = __shfl_sync(0xffffffffu, mine, base + 3);
    float p4 = __shfl_sync(0xffffffffu, mine, base + 4);

    if (store_ok)
        out[elem] = ((mine + p1) + (p2 + p3)) + (p4 + s[S_BR]);
}

extern "C" void kernel_launch(void* const* d_in, const int* in_sizes, int n_in,
                              void* d_out, int out_size)
{
    const float* x  = (const float*)d_in[0];
    const float* Wf = (const float*)d_in[1];
    const float* bf = (const float*)d_in[2];
    const float* Wm = (const float*)d_in[3];
    const float* bm = (const float*)d_in[4];
    const float* Wu = (const float*)d_in[5];
    const float* bu = (const float*)d_in[6];
    const float* Wr = (const float*)d_in[7];
    const float* br = (const float*)d_in[8];
    float* out = (float*)d_out;

    const int n = in_sizes[0] / 30;          // B  (x is [B,5,6])
    const int elems_per_block = 24;          // 4 warps x 6 groups
    const int blocks = (n + elems_per_block - 1) / elems_per_block;
    mp_kernel<<<blocks, 128>>>(x, Wf, bf, Wm, bm, Wu, bu, Wr, br, out, n);
}

// round 5
// speedup vs baseline: 1.2134x; 1.2134x over previous
#include <cuda_runtime.h>

#define NH 18
#define NP 9
#define RW 20    // padded weight-row width (floats) = 80B -> rows 16B-aligned
#define BT 96    // threads per block

typedef unsigned long long u64;

// ---- smem float offsets ----
#define S_WF   0      // 6  rows x RW
#define S_WM   120    // 36 rows x RW
#define S_WUM  840    // 18 rows (Wu rows 0..17, message part)
#define S_WUH  1200   // 18 rows (Wu[18:36]+Wu[36:54] folded; U==h there)
#define S_WR   1560   // 5 rows x RW
#define S_BF   1660
#define S_BM   1680
#define S_BU   1700
#define S_BR   1720
#define S_H    1728   // h storage: [ (node*18+e) * BT + tid ], 90*BT floats
#define S_TOT  (S_H + 90*BT)

__device__ __forceinline__ u64 dup2(float v){
    u64 r; asm("mov.b64 %0, {%1,%1};" : "=l"(r) : "f"(v)); return r;
}
__device__ __forceinline__ u64 pk2(float lo, float hi){
    u64 r; asm("mov.b64 %0, {%1,%2};" : "=l"(r) : "f"(lo), "f"(hi)); return r;
}
__device__ __forceinline__ void upk2(u64 v, float& lo, float& hi){
    asm("mov.b64 {%0,%1}, %2;" : "=f"(lo), "=f"(hi) : "l"(v));
}
__device__ __forceinline__ u64 fma2(u64 a, u64 b, u64 c){
    u64 d; asm("fma.rn.f32x2 %0, %1, %2, %3;" : "=l"(d) : "l"(a), "l"(b), "l"(c));
    return d;
}
__device__ __forceinline__ float tanhap(float x){
    float r; asm("tanh.approx.f32 %0, %1;" : "=f"(r) : "f"(x)); return r;
}

// 18-float weight row as 9 u64 pairs (broadcast, conflict-free)
__device__ __forceinline__ void ldrow9(const float* s, int off, u64 w[NP]){
    ulonglong2 q0 = *(const ulonglong2*)(s + off);
    ulonglong2 q1 = *(const ulonglong2*)(s + off + 4);
    ulonglong2 q2 = *(const ulonglong2*)(s + off + 8);
    ulonglong2 q3 = *(const ulonglong2*)(s + off + 12);
    w[0]=q0.x; w[1]=q0.y; w[2]=q1.x; w[3]=q1.y;
    w[4]=q2.x; w[5]=q2.y; w[6]=q3.x; w[7]=q3.y;
    w[8] = *(const u64*)(s + off + 16);
}
// pairs 0..3 (floats 0..7)
__device__ __forceinline__ void ldrowA(const float* s, int off, u64 w[4]){
    ulonglong2 q0 = *(const ulonglong2*)(s + off);
    ulonglong2 q1 = *(const ulonglong2*)(s + off + 4);
    w[0]=q0.x; w[1]=q0.y; w[2]=q1.x; w[3]=q1.y;
}
// pairs 4..8 (floats 8..17)
__device__ __forceinline__ void ldrowB(const float* s, int off, u64 w[5]){
    ulonglong2 q0 = *(const ulonglong2*)(s + off + 8);
    ulonglong2 q1 = *(const ulonglong2*)(s + off + 12);
    w[0]=q0.x; w[1]=q0.y; w[2]=q1.x; w[3]=q1.y;
    w[4] = *(const u64*)(s + off + 16);
}

__global__ void __launch_bounds__(BT, 4) mp_kernel(
    const float* __restrict__ x,
    const float* __restrict__ Wf, const float* __restrict__ bf,
    const float* __restrict__ Wm, const float* __restrict__ bm,
    const float* __restrict__ Wu, const float* __restrict__ bu,
    const float* __restrict__ Wr, const float* __restrict__ br,
    float* __restrict__ out, int n)
{
    __shared__ __align__(16) float s[S_TOT];
    const int t = threadIdx.x;
    for (int k = t; k < 6*NH;  k += BT){ int r=k/NH, c=k%NH; s[S_WF + r*RW + c] = Wf[k]; }
    for (int k = t; k < 36*NH; k += BT){ int r=k/NH, c=k%NH; s[S_WM + r*RW + c] = Wm[k]; }
    for (int k = t; k < 18*NH; k += BT){
        int r=k/NH, c=k%NH;
        s[S_WUM + r*RW + c] = Wu[k];
        s[S_WUH + r*RW + c] = Wu[324 + k] + Wu[648 + k];   // fold duplicated h columns
    }
    for (int k = t; k < 90; k += BT){ int r=k/NH, c=k%NH; s[S_WR + r*RW + c] = Wr[k]; }
    if (t < NH){ s[S_BF+t] = bf[t]; s[S_BM+t] = bm[t]; s[S_BU+t] = bu[t]; }
    if (t == 0) s[S_BR] = br[0];
    __syncthreads();

    const int b = blockIdx.x * BT + t;
    if (b >= n) return;

    float* H = s + S_H + t;                // this thread's h slots, stride BT
    #define HS(i,e) H[((i)*NH + (e)) * BT]

    // ---- x[b]: 30 floats, 8B-aligned ----
    float xv[30];
    {
        const float2* xb = (const float2*)(x + (long long)b * 30);
        #pragma unroll
        for (int k = 0; k < 15; k++){ float2 v = xb[k]; xv[2*k]=v.x; xv[2*k+1]=v.y; }
    }

    // ======== layer 1: h_i = tanh(x_i @ Wf + bf), store to smem ========
    {
        u64 acc[5][NP];
        {
            u64 bb[NP]; ldrow9(s, S_BF, bb);
            #pragma unroll
            for (int p = 0; p < NP; p++){
                #pragma unroll
                for (int i = 0; i < 5; i++) acc[i][p] = bb[p];
            }
        }
        #pragma unroll
        for (int f = 0; f < 6; f++){
            u64 w[NP]; ldrow9(s, S_WF + f*RW, w);
            #pragma unroll
            for (int i = 0; i < 5; i++){
                u64 a = dup2(xv[i*6 + f]);
                #pragma unroll
                for (int p = 0; p < NP; p++) acc[i][p] = fma2(a, w[p], acc[i][p]);
            }
        }
        #pragma unroll
        for (int i = 0; i < 5; i++){
            #pragma unroll
            for (int p = 0; p < NP; p++){
                float lo, hi; upk2(acc[i][p], lo, hi);
                HS(i, 2*p)   = tanhap(lo);
                HS(i, 2*p+1) = tanhap(hi);
            }
        }
    }

    // ======== layer M: M_i = tanh([h_i, h_{i+1}] @ Wm + bm), M in regs ========
    float M[5][NH];
    {
        u64 acc[5][NP];
        {
            u64 bb[NP]; ldrow9(s, S_BM, bb);
            #pragma unroll
            for (int p = 0; p < NP; p++){
                #pragma unroll
                for (int i = 0; i < 5; i++) acc[i][p] = bb[p];
            }
        }
        #pragma unroll
        for (int e = 0; e < NH; e++){                 // rows [0,18): h_i
            u64 w[NP]; ldrow9(s, S_WM + e*RW, w);
            #pragma unroll
            for (int i = 0; i < 5; i++){
                u64 a = dup2(HS(i, e));
                #pragma unroll
                for (int p = 0; p < NP; p++) acc[i][p] = fma2(a, w[p], acc[i][p]);
            }
        }
        #pragma unroll
        for (int e = 0; e < NH; e++){                 // rows [18,36): h_{i+1}
            u64 w[NP]; ldrow9(s, S_WM + (NH+e)*RW, w);
            #pragma unroll
            for (int i = 0; i < 5; i++){
                u64 a = dup2(HS((i+1)%5, e));
                #pragma unroll
                for (int p = 0; p < NP; p++) acc[i][p] = fma2(a, w[p], acc[i][p]);
            }
        }
        #pragma unroll
        for (int i = 0; i < 5; i++){
            #pragma unroll
            for (int p = 0; p < NP; p++){
                float lo, hi; upk2(acc[i][p], lo, hi);
                M[i][2*p]   = tanhap(lo);
                M[i][2*p+1] = tanhap(hi);
            }
        }
    }

    // ======== layer U + readout, channel-split two-pass ========
    // U_i = tanh(M_{i-1} @ WuM + h_i @ WuH + bu);  out += U_i . Wr[i]
    u64 racc = 0;

    // ---- pass A: pairs 0..3 ----
    {
        u64 acc[5][4];
        {
            u64 bb[4]; ldrowA(s, S_BU, bb);
            #pragma unroll
            for (int p = 0; p < 4; p++){
                #pragma unroll
                for (int i = 0; i < 5; i++) acc[i][p] = bb[p];
            }
        }
        #pragma unroll
        for (int e = 0; e < NH; e++){
            u64 w[4]; ldrowA(s, S_WUM + e*RW, w);
            #pragma unroll
            for (int i = 0; i < 5; i++){
                u64 a = dup2(M[(i+4)%5][e]);
                #pragma unroll
                for (int p = 0; p < 4; p++) acc[i][p] = fma2(a, w[p], acc[i][p]);
            }
        }
        #pragma unroll
        for (int e = 0; e < NH; e++){
            u64 w[4]; ldrowA(s, S_WUH + e*RW, w);
            #pragma unroll
            for (int i = 0; i < 5; i++){
                u64 a = dup2(HS(i, e));
                #pragma unroll
                for (int p = 0; p < 4; p++) acc[i][p] = fma2(a, w[p], acc[i][p]);
            }
        }
        #pragma unroll
        for (int i = 0; i < 5; i++){
            u64 wr[4]; ldrowA(s, S_WR + i*RW, wr);
            #pragma unroll
            for (int p = 0; p < 4; p++){
                float lo, hi; upk2(acc[i][p], lo, hi);
                u64 u2 = pk2(tanhap(lo), tanhap(hi));
                racc = fma2(u2, wr[p], racc);
            }
        }
    }

    // ---- pass B: pairs 4..8 ----
    {
        u64 acc[5][5];
        {
            u64 bb[5]; ldrowB(s, S_BU, bb);
            #pragma unroll
            for (int p = 0; p < 5; p++){
                #pragma unroll
                for (int i = 0; i < 5; i++) acc[i][p] = bb[p];
            }
        }
        #pragma unroll
        for (int e = 0; e < NH; e++){
            u64 w[5]; ldrowB(s, S_WUM + e*RW, w);
            #pragma unroll
            for (int i = 0; i < 5; i++){
                u64 a = dup2(M[(i+4)%5][e]);
                #pragma unroll
                for (int p = 0; p < 5; p++) acc[i][p] = fma2(a, w[p], acc[i][p]);
            }
        }
        #pragma unroll
        for (int e = 0; e < NH; e++){
            u64 w[5]; ldrowB(s, S_WUH + e*RW, w);
            #pragma unroll
            for (int i = 0; i < 5; i++){
                u64 a = dup2(HS(i, e));
                #pragma unroll
                for (int p = 0; p < 5; p++) acc[i][p] = fma2(a, w[p], acc[i][p]);
            }
        }
        #pragma unroll
        for (int i = 0; i < 5; i++){
            u64 wr[5]; ldrowB(s, S_WR + i*RW, wr);
            #pragma unroll
            for (int p = 0; p < 5; p++){
                float lo, hi; upk2(acc[i][p], lo, hi);
                u64 u2 = pk2(tanhap(lo), tanhap(hi));
                racc = fma2(u2, wr[p], racc);
            }
        }
    }

    float r0, r1; upk2(racc, r0, r1);
    out[b] = r0 + r1 + s[S_BR];
    #undef HS
}

extern "C" void kernel_launch(void* const* d_in, const int* in_sizes, int n_in,
                              void* d_out, int out_size)
{
    const float* x  = (const float*)d_in[0];
    const float* Wf = (const float*)d_in[1];
    const float* bf = (const float*)d_in[2];
    const float* Wm = (const float*)d_in[3];
    const float* bm = (const float*)d_in[4];
    const float* Wu = (const float*)d_in[5];
    const float* bu = (const float*)d_in[6];
    const float* Wr = (const float*)d_in[7];
    const float* br = (const float*)d_in[8];
    float* out = (float*)d_out;

    const int n = in_sizes[0] / 30;     // B  (x is [B,5,6])
    const int blocks = (n + BT - 1) / BT;
    mp_kernel<<<blocks, BT>>>(x, Wf, bf, Wm, bm, Wu, bu, Wr, br, out, n);
}

// round 6
// speedup vs baseline: 1.5305x; 1.2614x over previous
#include <cuda_runtime.h>

#define NH 18
#define NP 9
#define RW 20    // padded weight-row width (floats) = 80B -> rows 16B-aligned
#define BT 128   // threads per block

typedef unsigned long long u64;

// ---- smem float offsets ----
#define S_WF   0      // 6  rows x RW
#define S_WM   120    // 36 rows x RW
#define S_WUM  840    // 18 rows (Wu rows 0..17, message part)
#define S_WUH  1200   // 18 rows (Wu[18:36]+Wu[36:54] folded; U==h there)
#define S_WR   1560   // 5 rows x RW
#define S_BF   1660
#define S_BM   1680
#define S_BU   1700
#define S_BR   1720
#define S_H    1728   // h: [ (node*18+e) * BT + tid ], 90*BT floats
#define S_TOTF (S_H + 90*BT)               // total floats
#define SMEM_BYTES (S_TOTF * 4)            // 52992 B -> needs dynamic smem attr

__device__ __forceinline__ u64 dup2(float v){
    u64 r; asm("mov.b64 %0, {%1,%1};" : "=l"(r) : "f"(v)); return r;
}
__device__ __forceinline__ u64 pk2(float lo, float hi){
    u64 r; asm("mov.b64 %0, {%1,%2};" : "=l"(r) : "f"(lo), "f"(hi)); return r;
}
__device__ __forceinline__ void upk2(u64 v, float& lo, float& hi){
    asm("mov.b64 {%0,%1}, %2;" : "=f"(lo), "=f"(hi) : "l"(v));
}
__device__ __forceinline__ u64 fma2(u64 a, u64 b, u64 c){
    u64 d; asm("fma.rn.f32x2 %0, %1, %2, %3;" : "=l"(d) : "l"(a), "l"(b), "l"(c));
    return d;
}
__device__ __forceinline__ float tanhap(float x){
    float r; asm("tanh.approx.f32 %0, %1;" : "=f"(r) : "f"(x)); return r;
}

// 18-float weight row as 9 u64 pairs (broadcast, conflict-free)
__device__ __forceinline__ void ldrow9(const float* s, int off, u64 w[NP]){
    ulonglong2 q0 = *(const ulonglong2*)(s + off);
    ulonglong2 q1 = *(const ulonglong2*)(s + off + 4);
    ulonglong2 q2 = *(const ulonglong2*)(s + off + 8);
    ulonglong2 q3 = *(const ulonglong2*)(s + off + 12);
    w[0]=q0.x; w[1]=q0.y; w[2]=q1.x; w[3]=q1.y;
    w[4]=q2.x; w[5]=q2.y; w[6]=q3.x; w[7]=q3.y;
    w[8] = *(const u64*)(s + off + 16);
}

__global__ void __launch_bounds__(BT, 2) mp_kernel(
    const float* __restrict__ x,
    const float* __restrict__ Wf, const float* __restrict__ bf,
    const float* __restrict__ Wm, const float* __restrict__ bm,
    const float* __restrict__ Wu, const float* __restrict__ bu,
    const float* __restrict__ Wr, const float* __restrict__ br,
    float* __restrict__ out, int n)
{
    extern __shared__ __align__(16) float s[];
    const int t = threadIdx.x;
    for (int k = t; k < 6*NH;  k += BT){ int r=k/NH, c=k%NH; s[S_WF + r*RW + c] = Wf[k]; }
    for (int k = t; k < 36*NH; k += BT){ int r=k/NH, c=k%NH; s[S_WM + r*RW + c] = Wm[k]; }
    for (int k = t; k < 18*NH; k += BT){
        int r=k/NH, c=k%NH;
        s[S_WUM + r*RW + c] = Wu[k];
        s[S_WUH + r*RW + c] = Wu[324 + k] + Wu[648 + k];   // fold duplicated h columns
    }
    for (int k = t; k < 90; k += BT){ int r=k/NH, c=k%NH; s[S_WR + r*RW + c] = Wr[k]; }
    if (t < NH){ s[S_BF+t] = bf[t]; s[S_BM+t] = bm[t]; s[S_BU+t] = bu[t]; }
    if (t == 0) s[S_BR] = br[0];
    __syncthreads();

    const int b = blockIdx.x * BT + t;
    if (b >= n) return;

    float* H = s + S_H + t;                 // this thread's h slots, stride BT
    #define HS(i,e) H[((i)*NH + (e)) * BT]

    // ---- x[b]: 30 floats, 8B-aligned ----
    float xv[30];
    {
        const float2* xb = (const float2*)(x + (long long)b * 30);
        #pragma unroll
        for (int k = 0; k < 15; k++){ float2 v = xb[k]; xv[2*k]=v.x; xv[2*k+1]=v.y; }
    }

    // ======== layer 1: h_i = tanh(x_i @ Wf + bf) -> smem ========
    {
        u64 acc[5][NP];
        {
            u64 bb[NP]; ldrow9(s, S_BF, bb);
            #pragma unroll
            for (int p = 0; p < NP; p++){
                #pragma unroll
                for (int i = 0; i < 5; i++) acc[i][p] = bb[p];
            }
        }
        #pragma unroll
        for (int f = 0; f < 6; f++){
            u64 w[NP]; ldrow9(s, S_WF + f*RW, w);
            #pragma unroll
            for (int i = 0; i < 5; i++){
                u64 a = dup2(xv[i*6 + f]);
                #pragma unroll
                for (int p = 0; p < NP; p++) acc[i][p] = fma2(a, w[p], acc[i][p]);
            }
        }
        #pragma unroll
        for (int i = 0; i < 5; i++){
            #pragma unroll
            for (int p = 0; p < NP; p++){
                float lo, hi; upk2(acc[i][p], lo, hi);
                HS(i, 2*p)   = tanhap(lo);
                HS(i, 2*p+1) = tanhap(hi);
            }
        }
    }

    // ======== layer M (e-fused): accM[i] = bm + sum_e Wm[e]*h_i[e] + Wm[18+e]*h_{i+1}[e]
    //          each h_i[e] loaded ONCE: feeds edge i (row e) and edge i-1 (row 18+e) ========
    float M[5][NH];
    {
        u64 acc[5][NP];
        {
            u64 bb[NP]; ldrow9(s, S_BM, bb);
            #pragma unroll
            for (int p = 0; p < NP; p++){
                #pragma unroll
                for (int i = 0; i < 5; i++) acc[i][p] = bb[p];
            }
        }
        #pragma unroll
        for (int e = 0; e < NH; e++){
            u64 w1[NP]; ldrow9(s, S_WM + e*RW, w1);          // h_i part
            u64 w2[NP]; ldrow9(s, S_WM + (NH+e)*RW, w2);     // h_{i+1} part
            float hv[5];
            #pragma unroll
            for (int i = 0; i < 5; i++) hv[i] = HS(i, e);
            #pragma unroll
            for (int i = 0; i < 5; i++){
                u64 a = dup2(hv[i]);
                #pragma unroll
                for (int p = 0; p < NP; p++) acc[i][p] = fma2(a, w1[p], acc[i][p]);
                const int j = (i + 4) % 5;                   // edge j has h_{j+1} = h_i
                #pragma unroll
                for (int p = 0; p < NP; p++) acc[j][p] = fma2(a, w2[p], acc[j][p]);
            }
        }
        #pragma unroll
        for (int i = 0; i < 5; i++){
            #pragma unroll
            for (int p = 0; p < NP; p++){
                float lo, hi; upk2(acc[i][p], lo, hi);
                M[i][2*p]   = tanhap(lo);
                M[i][2*p+1] = tanhap(hi);
            }
        }
    }

    // ======== layer U (single pass): accU[i] = bu + sum_e WuM[e]*M_{i-1}[e] + WuH[e]*h_i[e] ========
    u64 racc = 0;
    {
        u64 acc[5][NP];
        {
            u64 bb[NP]; ldrow9(s, S_BU, bb);
            #pragma unroll
            for (int p = 0; p < NP; p++){
                #pragma unroll
                for (int i = 0; i < 5; i++) acc[i][p] = bb[p];
            }
        }
        #pragma unroll
        for (int e = 0; e < NH; e++){
            u64 w1[NP]; ldrow9(s, S_WUM + e*RW, w1);
            u64 w2[NP]; ldrow9(s, S_WUH + e*RW, w2);
            #pragma unroll
            for (int i = 0; i < 5; i++){
                u64 am = dup2(M[(i+4)%5][e]);
                #pragma unroll
                for (int p = 0; p < NP; p++) acc[i][p] = fma2(am, w1[p], acc[i][p]);
                u64 ah = dup2(HS(i, e));
                #pragma unroll
                for (int p = 0; p < NP; p++) acc[i][p] = fma2(ah, w2[p], acc[i][p]);
            }
        }
        // readout: out += tanh(accU_i) . Wr[i]
        #pragma unroll
        for (int i = 0; i < 5; i++){
            u64 wr[NP]; ldrow9(s, S_WR + i*RW, wr);
            #pragma unroll
            for (int p = 0; p < NP; p++){
                float lo, hi; upk2(acc[i][p], lo, hi);
                u64 u2 = pk2(tanhap(lo), tanhap(hi));
                racc = fma2(u2, wr[p], racc);
            }
        }
    }

    float r0, r1; upk2(racc, r0, r1);
    out[b] = r0 + r1 + s[S_BR];
    #undef HS
}

extern "C" void kernel_launch(void* const* d_in, const int* in_sizes, int n_in,
                              void* d_out, int out_size)
{
    const float* x  = (const float*)d_in[0];
    const float* Wf = (const float*)d_in[1];
    const float* bf = (const float*)d_in[2];
    const float* Wm = (const float*)d_in[3];
    const float* bm = (const float*)d_in[4];
    const float* Wu = (const float*)d_in[5];
    const float* bu = (const float*)d_in[6];
    const float* Wr = (const float*)d_in[7];
    const float* br = (const float*)d_in[8];
    float* out = (float*)d_out;

    // >48KB dynamic smem: set attribute every call (idempotent, capture-safe)
    cudaFuncSetAttribute(mp_kernel, cudaFuncAttributeMaxDynamicSharedMemorySize,
                         SMEM_BYTES);

    const int n = in_sizes[0] / 30;     // B  (x is [B,5,6])
    const int blocks = (n + BT - 1) / BT;
    mp_kernel<<<blocks, BT, SMEM_BYTES>>>(x, Wf, bf, Wm, bm, Wu, bu, Wr, br, out, n);
}